// round 6
// baseline (speedup 1.0000x reference)
#include <cuda_runtime.h>

// SKA: out[b, g*32+c, h, w] = sum_{di,dj} x[b, g*32+c, h+di-2, w+dj-2] * w[b, g, di*5+dj, h, w]
// x [8,256,64,64] f32, w [8,8,25,64,64] f32, out [8,256,64,64] f32.
//
// Thread = 8 px x 1 channel x 2 rows (16 outputs). Block = (b,g) x 2 rows x 32 ch x 64 px.
// w tile [25][2][64] in smem; warp = 8 px-groups x 4 channels so each w LDS.128 is a
// single conflict-free broadcast wavefront. x loaded as 4 aligned LDG.128 per row
// covering cols [w0-4, w0+11]; one 16-reg window serves both output rows.

#define B_  8
#define C_  256
#define H_  64
#define W_  64
#define G_  8
#define CG_ 32
#define RH_ 2
#define PX_ 8

__global__ __launch_bounds__(256, 4)
void SKA_60387240182286_kernel(const float* __restrict__ x,
                               const float* __restrict__ wgt,
                               float* __restrict__ out)
{
    __shared__ float ws[25 * RH_ * W_];   // [k][rr][w] = 12.8 KB

    const int tid = threadIdx.x;
    const int wqg = tid & 7;              // 0..7: 8-wide pixel group
    const int ch  = tid >> 3;             // 0..31: channel within group

    const int bg = blockIdx.x;            // b*8 + g
    const int h0 = blockIdx.y * RH_;
    const int b  = bg >> 3;
    const int g  = bg & 7;
    const int w0 = wqg * PX_;             // 0,8,...,56
    const int c  = g * CG_ + ch;

    // ---- stage w tile: rows h0..h0+1, all 25 taps (each tap-row: 64 contiguous floats)
    {
        const float* wsrc = wgt + (((size_t)bg * 25) * H_ + h0) * W_;
        float4* wsv = (float4*)ws;
#pragma unroll
        for (int i = tid; i < 800; i += 256) {   // 800 float4
            const int k = i >> 5;                 // tap (32 float4 per tap = 2 rows)
            const int r = i & 31;                 // float4 within the 2-row chunk
            wsv[i] = *(const float4*)(wsrc + (size_t)k * (H_ * W_) + r * 4);
        }
    }
    __syncthreads();

    const float* xrow0 = x + ((size_t)(b * C_ + c) * H_) * W_;

    float acc[RH_][PX_];
#pragma unroll
    for (int r = 0; r < RH_; ++r)
#pragma unroll
        for (int p = 0; p < PX_; ++p) acc[r][p] = 0.f;

    const float4 z4 = make_float4(0.f, 0.f, 0.f, 0.f);
    const bool left_edge  = (wqg == 0);
    const bool right_edge = (wqg == 7);

#pragma unroll
    for (int hi = 0; hi < RH_ + 4; ++hi) {        // x row hy = h0 - 2 + hi
        const int hy = h0 - 2 + hi;
        const bool rv = (hy >= 0) && (hy < H_);

        // x window: 16 floats covering cols [w0-4, w0+11] (4 aligned float4)
        const float* row = xrow0 + (size_t)hy * W_;
        float4 f0 = (rv && !left_edge)  ? *(const float4*)(row + w0 - 4) : z4;
        float4 f1 = rv                  ? *(const float4*)(row + w0)     : z4;
        float4 f2 = rv                  ? *(const float4*)(row + w0 + 4) : z4;
        float4 f3 = (rv && !right_edge) ? *(const float4*)(row + w0 + 8) : z4;
        float xv[16] = { f0.x, f0.y, f0.z, f0.w,  f1.x, f1.y, f1.z, f1.w,
                         f2.x, f2.y, f2.z, f2.w,  f3.x, f3.y, f3.z, f3.w };

        // this x row feeds output row rr where di = hi - rr in [0,4]
#pragma unroll
        for (int rr = 0; rr < RH_; ++rr) {
            const int di = hi - rr;
            if (di < 0 || di > 4) continue;       // compile-time prune
#pragma unroll
            for (int dj = 0; dj < 5; ++dj) {
                const int k = di * 5 + dj;
                const float* wrow = ws + (k * RH_ + rr) * W_ + w0;
                const float4 wa = *(const float4*)(wrow);      // w for px 0..3
                const float4 wb = *(const float4*)(wrow + 4);  // w for px 4..7
                // output px p (col w0+p), tap dj -> x col w0+p+dj-2 -> idx p+dj+2
                acc[rr][0] = fmaf(xv[dj + 2],  wa.x, acc[rr][0]);
                acc[rr][1] = fmaf(xv[dj + 3],  wa.y, acc[rr][1]);
                acc[rr][2] = fmaf(xv[dj + 4],  wa.z, acc[rr][2]);
                acc[rr][3] = fmaf(xv[dj + 5],  wa.w, acc[rr][3]);
                acc[rr][4] = fmaf(xv[dj + 6],  wb.x, acc[rr][4]);
                acc[rr][5] = fmaf(xv[dj + 7],  wb.y, acc[rr][5]);
                acc[rr][6] = fmaf(xv[dj + 8],  wb.z, acc[rr][6]);
                acc[rr][7] = fmaf(xv[dj + 9],  wb.w, acc[rr][7]);
            }
        }
    }

    float* obase = out + (((size_t)(b * C_ + c) * H_) + h0) * W_ + w0;
#pragma unroll
    for (int r = 0; r < RH_; ++r) {
        *(float4*)(obase + (size_t)r * W_) =
            make_float4(acc[r][0], acc[r][1], acc[r][2], acc[r][3]);
        *(float4*)(obase + (size_t)r * W_ + 4) =
            make_float4(acc[r][4], acc[r][5], acc[r][6], acc[r][7]);
    }
}

extern "C" void kernel_launch(void* const* d_in, const int* in_sizes, int n_in,
                              void* d_out, int out_size)
{
    const float* x   = (const float*)d_in[0];
    const float* wgt = (const float*)d_in[1];
    float* out = (float*)d_out;

    dim3 grid(B_ * G_, H_ / RH_);   // (64, 32) = 2048 blocks
    SKA_60387240182286_kernel<<<grid, 256>>>(x, wgt, out);
}

// round 7
// speedup vs baseline: 1.9154x; 1.9154x over previous
#include <cuda_runtime.h>

// SKA: out[b, g*32+c, h, w] = sum_{di,dj} x[b, g*32+c, h+di-2, w+dj-2] * w[b, g, di*5+dj, h, w]
// x [8,256,64,64] f32, w [8,8,25,64,64] f32, out [8,256,64,64] f32.
//
// Thread = 4px x 2ch x 2rows. Warp = 8wq x 4cpi -> each w LDS.128 is one
// conflict-free 128B broadcast wavefront. w tile [25][2][64] in smem.
// x loads double-buffered (prefetch row hi+1 before computing row hi).
// Interior/edge split: interior blocks (30/32) have no vertical predication.
// All inner addresses are compile-time immediate offsets off single bases.

#define B_  8
#define C_  256
#define H_  64
#define W_  64
#define G_  8
#define CG_ 32
#define NC_ 2
#define RH_ 2
#define HW_ (H_ * W_)

template<bool EDGE>
__global__ __launch_bounds__(256, 4)
void ska_kernel(const float* __restrict__ x,
                const float* __restrict__ wgt,
                float* __restrict__ out)
{
    __shared__ float ws[25 * RH_ * W_];   // [k][rr][w] = 12.8 KB

    const int tid    = threadIdx.x;
    const int lane   = tid & 31;
    const int warp   = tid >> 5;
    const int wq_lo  = lane & 7;
    const int cpi_lo = lane >> 3;
    const int wq_hi  = warp & 1;
    const int cpi_hi = warp >> 1;
    const int wq  = wq_lo + 8 * wq_hi;    // 0..15
    const int cpi = cpi_lo + 4 * cpi_hi;  // 0..15

    const int bg    = blockIdx.x;         // b*8 + g
    const int hpair = EDGE ? (blockIdx.y * 31) : (blockIdx.y + 1);
    const int h0    = hpair * RH_;
    const int b = bg >> 3;
    const int g = bg & 7;
    const int w0 = wq * 4;
    const int c0 = g * CG_ + cpi * NC_;

    // ---- stage w tile: rows h0..h0+1, all 25 taps
    {
        const float* wsrc = wgt + (((size_t)bg * 25) * H_ + h0) * W_;
        float4* wsv = (float4*)ws;
#pragma unroll
        for (int i = tid; i < 800; i += 256) {
            const int k = i >> 5;
            const int r = i & 31;
            wsv[i] = *(const float4*)(wsrc + (size_t)k * HW_ + r * 4);
        }
    }
    __syncthreads();

    // single base; all per-(c,hi) offsets are compile-time immediates
    const float* xb = x + (((size_t)(b * C_ + c0)) * H_ + (h0 - 2)) * W_ + w0;
    const float* wsb = ws + w0;           // + (k*RH + rr)*W_ immediates

    float acc[RH_][NC_][4];
#pragma unroll
    for (int r = 0; r < RH_; ++r)
#pragma unroll
        for (int c = 0; c < NC_; ++c) {
            acc[r][c][0] = 0.f; acc[r][c][1] = 0.f;
            acc[r][c][2] = 0.f; acc[r][c][3] = 0.f;
        }

    const float2 z2 = make_float2(0.f, 0.f);
    const float4 z4 = make_float4(0.f, 0.f, 0.f, 0.f);
    const bool left_edge  = (wq == 0);
    const bool right_edge = (wq == 15);

    float xv[2][NC_][8];                  // double-buffered window, cols [w0-2, w0+5]

    // prologue: row hi=0 (hy = h0-2)
    {
        const bool rv = !EDGE || (h0 - 2 >= 0);
#pragma unroll
        for (int c = 0; c < NC_; ++c) {
            const float* p = xb + c * HW_;
            float2 a = (rv && !left_edge)  ? *(const float2*)(p - 2) : z2;
            float4 m = rv                  ? *(const float4*)(p)     : z4;
            float2 r = (rv && !right_edge) ? *(const float2*)(p + 4) : z2;
            xv[0][c][0] = a.x; xv[0][c][1] = a.y;
            xv[0][c][2] = m.x; xv[0][c][3] = m.y; xv[0][c][4] = m.z; xv[0][c][5] = m.w;
            xv[0][c][6] = r.x; xv[0][c][7] = r.y;
        }
    }

#pragma unroll
    for (int hi = 0; hi < RH_ + 4; ++hi) {
        const int cur = hi & 1;
        const int nxt = cur ^ 1;

        // prefetch row hi+1
        if (hi < RH_ + 3) {
            const int hyn = h0 - 1 + hi;
            const bool rvn = !EDGE || ((hyn >= 0) && (hyn < H_));
#pragma unroll
            for (int c = 0; c < NC_; ++c) {
                const float* p = xb + c * HW_ + (hi + 1) * W_;
                float2 a = (rvn && !left_edge)  ? *(const float2*)(p - 2) : z2;
                float4 m = rvn                  ? *(const float4*)(p)     : z4;
                float2 r = (rvn && !right_edge) ? *(const float2*)(p + 4) : z2;
                xv[nxt][c][0] = a.x; xv[nxt][c][1] = a.y;
                xv[nxt][c][2] = m.x; xv[nxt][c][3] = m.y;
                xv[nxt][c][4] = m.z; xv[nxt][c][5] = m.w;
                xv[nxt][c][6] = r.x; xv[nxt][c][7] = r.y;
            }
        }

        // compute with row hi
#pragma unroll
        for (int rr = 0; rr < RH_; ++rr) {
            const int di = hi - rr;
            if (di < 0 || di > 4) continue;       // compile-time prune
#pragma unroll
            for (int dj = 0; dj < 5; ++dj) {
                const int k = di * 5 + dj;
                const float4 wv = *(const float4*)(wsb + (k * RH_ + rr) * W_);
#pragma unroll
                for (int c = 0; c < NC_; ++c) {
                    acc[rr][c][0] = fmaf(xv[cur][c][dj + 0], wv.x, acc[rr][c][0]);
                    acc[rr][c][1] = fmaf(xv[cur][c][dj + 1], wv.y, acc[rr][c][1]);
                    acc[rr][c][2] = fmaf(xv[cur][c][dj + 2], wv.z, acc[rr][c][2]);
                    acc[rr][c][3] = fmaf(xv[cur][c][dj + 3], wv.w, acc[rr][c][3]);
                }
            }
        }
    }

    float* ob = out + (((size_t)(b * C_ + c0)) * H_ + h0) * W_ + w0;
#pragma unroll
    for (int r = 0; r < RH_; ++r)
#pragma unroll
        for (int c = 0; c < NC_; ++c) {
            *(float4*)(ob + c * HW_ + r * W_) =
                make_float4(acc[r][c][0], acc[r][c][1], acc[r][c][2], acc[r][c][3]);
        }
}

extern "C" void kernel_launch(void* const* d_in, const int* in_sizes, int n_in,
                              void* d_out, int out_size)
{
    const float* x   = (const float*)d_in[0];
    const float* wgt = (const float*)d_in[1];
    float* out = (float*)d_out;

    dim3 gridI(B_ * G_, 30);   // interior hpairs 1..30
    dim3 gridE(B_ * G_, 2);    // edge hpairs 0 and 31
    ska_kernel<false><<<gridI, 256>>>(x, wgt, out);
    ska_kernel<true ><<<gridE, 256>>>(x, wgt, out);
}